// round 1
// baseline (speedup 1.0000x reference)
#include <cuda_runtime.h>
#include <cuda_bf16.h>
#include <math.h>

#define N_NODES 50000
#define N_EDGES 800000
#define DIN 128
#define NH 4

// ---------------- scratch buffers (device globals; no allocation allowed) ----
__device__ float g_feat[(size_t)N_NODES * 256];   // GEMM output (max HF=256)
__device__ float g_bufA[(size_t)N_NODES * 128];   // layer activations
__device__ float g_bufB[(size_t)N_NODES * 256];   // layer activations / L4 out
__device__ float g_el[(size_t)N_NODES * NH];
__device__ float g_er[(size_t)N_NODES * NH];
__device__ unsigned g_m[(size_t)N_NODES * NH];    // ordered-uint max
__device__ float g_den[(size_t)N_NODES * NH];
__device__ float g_ebuf[(size_t)N_EDGES * NH];    // e -> ex -> alpha (in place)

// ---------------- helpers ----------------------------------------------------
__device__ __forceinline__ unsigned ford(float f) {
    unsigned u = __float_as_uint(f);
    return (u & 0x80000000u) ? ~u : (u | 0x80000000u);
}
__device__ __forceinline__ float ordf(unsigned u) {
    return (u & 0x80000000u) ? __uint_as_float(u & 0x7fffffffu) : __uint_as_float(~u);
}
__device__ __forceinline__ float lrelu(float v) { return v > 0.f ? v : 0.2f * v; }

__device__ __forceinline__ void red_add_v4(float* p, float4 v) {
    asm volatile("red.global.add.v4.f32 [%0], {%1,%2,%3,%4};"
                 :: "l"(p), "f"(v.x), "f"(v.y), "f"(v.z), "f"(v.w) : "memory");
}

// ---------------- GEMM: feat = h @ W  (K = 128 always) -----------------------
// block: 256 threads, 64 nodes x 128 cols. smem: W tile 64KB + h tile 32KB.
__global__ void gemm_kernel(const float* __restrict__ h, const float* __restrict__ W,
                            float* __restrict__ feat, int HF) {
    extern __shared__ float sm[];
    float* Ws = sm;                 // [128][128]
    float* hs = sm + 128 * 128;     // [64][128]
    const int ct = blockIdx.y;      // column tile (128 cols)
    const int n0 = blockIdx.x * 64;
    const int tid = threadIdx.x;

    // load W tile (128 rows x 128 cols of this column tile)
    for (int i = tid; i < 4096; i += 256) {
        int j = i * 4;
        int k = j >> 7, c = j & 127;
        *(float4*)&Ws[j] = *(const float4*)&W[(size_t)k * HF + ct * 128 + c];
    }
    // load h tile (64 nodes x 128)
    for (int i = tid; i < 2048; i += 256) {
        int j = i * 4;
        int nn = j >> 7, c = j & 127;
        int n = n0 + nn;
        float4 v = make_float4(0.f, 0.f, 0.f, 0.f);
        if (n < N_NODES) v = *(const float4*)&h[(size_t)n * DIN + c];
        *(float4*)&hs[j] = v;
    }
    __syncthreads();

    const int tx = tid & 31, ty = tid >> 5;
    float acc[8][4];
#pragma unroll
    for (int i = 0; i < 8; i++) { acc[i][0] = acc[i][1] = acc[i][2] = acc[i][3] = 0.f; }

#pragma unroll 4
    for (int k = 0; k < 128; k++) {
        float4 b = *(float4*)&Ws[k * 128 + tx * 4];
#pragma unroll
        for (int i = 0; i < 8; i++) {
            float a = hs[(ty * 8 + i) * 128 + k];
            acc[i][0] += a * b.x; acc[i][1] += a * b.y;
            acc[i][2] += a * b.z; acc[i][3] += a * b.w;
        }
    }
#pragma unroll
    for (int i = 0; i < 8; i++) {
        int n = n0 + ty * 8 + i;
        if (n < N_NODES)
            *(float4*)&feat[(size_t)n * HF + ct * 128 + tx * 4] =
                make_float4(acc[i][0], acc[i][1], acc[i][2], acc[i][3]);
    }
}

// ---------------- el/er: per (node, head) dot along F ------------------------
__global__ void elrer_kernel(const float* __restrict__ feat, const float* __restrict__ al,
                             const float* __restrict__ ar, float* __restrict__ el,
                             float* __restrict__ er, int F) {
    int g = blockIdx.x * blockDim.x + threadIdx.x;
    if (g >= N_NODES * NH) return;
    int n = g >> 2, hh = g & 3;
    const float* fr = feat + (size_t)n * NH * F + hh * F;
    const float* alr = al + hh * F;
    const float* arr = ar + hh * F;
    float sl = 0.f, sr = 0.f;
    for (int f = 0; f < F; f++) { float v = fr[f]; sl += v * alr[f]; sr += v * arr[f]; }
    el[g] = sl; er[g] = sr;
}

// ---------------- init: m=0(ordered -inf), den=0, out=bias -------------------
__global__ void init_kernel(unsigned* __restrict__ m, float* __restrict__ den,
                            float* __restrict__ out, const float* __restrict__ b, int HF) {
    int g = blockIdx.x * blockDim.x + threadIdx.x;
    int total = N_NODES * HF;
    if (g < N_NODES * NH) { m[g] = 0u; den[g] = 0.f; }
    if (g < total) out[g] = b[g % HF];
}

// ---------------- edge pass 1: e = lrelu(el[src]+er[dst]); atomicMax m[dst] --
__global__ void edge_e_max(const int* __restrict__ src, const int* __restrict__ dst,
                           const float* __restrict__ el, const float* __restrict__ er,
                           float* __restrict__ ebuf, unsigned* __restrict__ m) {
    int e = blockIdx.x * blockDim.x + threadIdx.x;
    if (e >= N_EDGES) return;
    int s = src[e], d = dst[e];
    float4 l = *(const float4*)&el[s * 4];
    float4 r = *(const float4*)&er[d * 4];
    float4 v;
    v.x = lrelu(l.x + r.x); v.y = lrelu(l.y + r.y);
    v.z = lrelu(l.z + r.z); v.w = lrelu(l.w + r.w);
    *(float4*)&ebuf[(size_t)e * 4] = v;
    atomicMax(&m[d * 4 + 0], ford(v.x));
    atomicMax(&m[d * 4 + 1], ford(v.y));
    atomicMax(&m[d * 4 + 2], ford(v.z));
    atomicMax(&m[d * 4 + 3], ford(v.w));
}

// ---------------- edge pass 2: ex = exp(e - m[dst]); atomicAdd den[dst] ------
__global__ void edge_expsum(const int* __restrict__ dst, float* __restrict__ ebuf,
                            const unsigned* __restrict__ m, float* __restrict__ den) {
    int e = blockIdx.x * blockDim.x + threadIdx.x;
    if (e >= N_EDGES) return;
    int d = dst[e];
    float4 v = *(float4*)&ebuf[(size_t)e * 4];
    uint4 mu = *(const uint4*)&m[d * 4];
    v.x = expf(v.x - ordf(mu.x));
    v.y = expf(v.y - ordf(mu.y));
    v.z = expf(v.z - ordf(mu.z));
    v.w = expf(v.w - ordf(mu.w));
    *(float4*)&ebuf[(size_t)e * 4] = v;
    atomicAdd(&den[d * 4 + 0], v.x);
    atomicAdd(&den[d * 4 + 1], v.y);
    atomicAdd(&den[d * 4 + 2], v.z);
    atomicAdd(&den[d * 4 + 3], v.w);
}

// ---------------- edge pass 3: alpha = ex / max(den[dst],1e-9) ---------------
__global__ void edge_alpha(const int* __restrict__ dst, float* __restrict__ ebuf,
                           const float* __restrict__ den) {
    int e = blockIdx.x * blockDim.x + threadIdx.x;
    if (e >= N_EDGES) return;
    int d = dst[e];
    float4 v = *(float4*)&ebuf[(size_t)e * 4];
    float4 dn = *(const float4*)&den[d * 4];
    v.x /= fmaxf(dn.x, 1e-9f);
    v.y /= fmaxf(dn.y, 1e-9f);
    v.z /= fmaxf(dn.z, 1e-9f);
    v.w /= fmaxf(dn.w, 1e-9f);
    *(float4*)&ebuf[(size_t)e * 4] = v;
}

// ---------------- edge pass 4: out[dst] += alpha * feat[src] -----------------
// one thread per (edge, 4 columns); warp = exactly one edge (HF/4 = 32) or half
// an edge (HF/4 = 64) so src/dst loads are warp-uniform broadcasts.
__global__ void edge_agg(const int* __restrict__ src, const int* __restrict__ dst,
                         const float* __restrict__ alpha, const float* __restrict__ feat,
                         float* __restrict__ out, int HF, int qshift, int hshift) {
    int g = blockIdx.x * blockDim.x + threadIdx.x;
    int e = g >> qshift;
    if (e >= N_EDGES) return;
    int q = g & ((1 << qshift) - 1);
    int s = src[e], d = dst[e];
    int hh = q >> hshift;
    float a = alpha[(size_t)e * 4 + hh];
    float4 v = *(const float4*)&feat[(size_t)s * HF + q * 4];
    v.x *= a; v.y *= a; v.z *= a; v.w *= a;
    red_add_v4(&out[(size_t)d * HF + q * 4], v);
}

// ---------------- activations ------------------------------------------------
__global__ void elu_kernel(float* __restrict__ x, int n) {
    int g = blockIdx.x * blockDim.x + threadIdx.x;
    if (g >= n) return;
    float v = x[g];
    x[g] = v > 0.f ? v : expm1f(v);
}

__global__ void mean_kernel(const float* __restrict__ out, float* __restrict__ y) {
    int g = blockIdx.x * blockDim.x + threadIdx.x;
    if (g >= N_NODES * 64) return;
    int n = g >> 6, f = g & 63;
    const float* r = out + (size_t)n * 256;
    y[g] = 0.25f * (r[f] + r[64 + f] + r[128 + f] + r[192 + f]);
}

// ---------------- host -------------------------------------------------------
static void run_layer(const float* hin, const float* W, const float* al, const float* ar,
                      const float* b, const int* src, const int* dst,
                      float* feat, float* el, float* er, unsigned* m, float* den,
                      float* ebuf, float* outbuf, int F) {
    const int HF = NH * F;
    dim3 ggrid((N_NODES + 63) / 64, HF / 128);
    gemm_kernel<<<ggrid, 256, 98304>>>(hin, W, feat, HF);
    elrer_kernel<<<(N_NODES * NH + 255) / 256, 256>>>(feat, al, ar, el, er, F);
    init_kernel<<<(N_NODES * HF + 255) / 256, 256>>>(m, den, outbuf, b, HF);
    edge_e_max<<<(N_EDGES + 255) / 256, 256>>>(src, dst, el, er, ebuf, m);
    edge_expsum<<<(N_EDGES + 255) / 256, 256>>>(dst, ebuf, m, den);
    edge_alpha<<<(N_EDGES + 255) / 256, 256>>>(dst, ebuf, den);
    const int qshift = (HF == 128) ? 5 : 6;
    const int hshift = (F == 32) ? 3 : 4;
    int total = N_EDGES << qshift;
    edge_agg<<<(total + 255) / 256, 256>>>(src, dst, ebuf, feat, outbuf, HF, qshift, hshift);
}

extern "C" void kernel_launch(void* const* d_in, const int* in_sizes, int n_in,
                              void* d_out, int out_size) {
    const float* x   = (const float*)d_in[0];
    const int*   src = (const int*)d_in[1];
    const int*   dst = (const int*)d_in[2];
    const float *W[4], *al[4], *ar[4], *bb[4];
    for (int i = 0; i < 4; i++) {
        W[i]  = (const float*)d_in[3 + i * 4];
        al[i] = (const float*)d_in[4 + i * 4];
        ar[i] = (const float*)d_in[5 + i * 4];
        bb[i] = (const float*)d_in[6 + i * 4];
    }

    float *feat, *A, *B, *el, *er, *den, *ebuf;
    unsigned* m;
    cudaGetSymbolAddress((void**)&feat, g_feat);
    cudaGetSymbolAddress((void**)&A,    g_bufA);
    cudaGetSymbolAddress((void**)&B,    g_bufB);
    cudaGetSymbolAddress((void**)&el,   g_el);
    cudaGetSymbolAddress((void**)&er,   g_er);
    cudaGetSymbolAddress((void**)&m,    g_m);
    cudaGetSymbolAddress((void**)&den,  g_den);
    cudaGetSymbolAddress((void**)&ebuf, g_ebuf);

    cudaFuncSetAttribute(gemm_kernel, cudaFuncAttributeMaxDynamicSharedMemorySize, 98304);

    // layer 1: x -> A
    run_layer(x, W[0], al[0], ar[0], bb[0], src, dst, feat, el, er, m, den, ebuf, A, 32);
    elu_kernel<<<(N_NODES * 128 + 255) / 256, 256>>>(A, N_NODES * 128);
    // layer 2: A -> B
    run_layer(A, W[1], al[1], ar[1], bb[1], src, dst, feat, el, er, m, den, ebuf, B, 32);
    elu_kernel<<<(N_NODES * 128 + 255) / 256, 256>>>(B, N_NODES * 128);
    // layer 3: B -> A
    run_layer(B, W[2], al[2], ar[2], bb[2], src, dst, feat, el, er, m, den, ebuf, A, 32);
    elu_kernel<<<(N_NODES * 128 + 255) / 256, 256>>>(A, N_NODES * 128);
    // layer 4: A -> B (H=4, F=64), then mean over heads -> d_out
    run_layer(A, W[3], al[3], ar[3], bb[3], src, dst, feat, el, er, m, den, ebuf, B, 64);
    mean_kernel<<<(N_NODES * 64 + 255) / 256, 256>>>(B, (float*)d_out);
}

// round 2
// speedup vs baseline: 1.7080x; 1.7080x over previous
#include <cuda_runtime.h>
#include <cuda_bf16.h>
#include <math.h>

#define N_NODES 50000
#define N_EDGES 800000
#define DIN 128
#define NH 4

// ---------------- scratch buffers -------------------------------------------
__device__ float g_feat[(size_t)N_NODES * 256];   // GEMM output (max HF=256)
__device__ float g_bufA[(size_t)N_NODES * 128];   // activations
__device__ float g_bufB[(size_t)N_NODES * 128];   // activations
__device__ float g_el[(size_t)N_NODES * NH];
__device__ float g_er[(size_t)N_NODES * NH];
__device__ int   g_cnt[N_NODES];                  // in-degree histogram
__device__ int   g_rptr[N_NODES + 1];             // CSR row pointers (by dst)
__device__ int   g_cursor[N_NODES];               // scatter cursors
__device__ int   g_bsum[256];                     // scan block sums
__device__ int   g_srcs[N_EDGES];                 // src ids sorted by dst

// ---------------- helpers ----------------------------------------------------
__device__ __forceinline__ float lrelu(float v) { return v > 0.f ? v : 0.2f * v; }

// ---------------- GEMM: feat = h @ W  (K = 128 always) -----------------------
__global__ void gemm_kernel(const float* __restrict__ h, const float* __restrict__ W,
                            float* __restrict__ feat, int HF) {
    extern __shared__ float sm[];
    float* Ws = sm;                 // [128][128]
    float* hs = sm + 128 * 128;     // [64][128]
    const int ct = blockIdx.y;
    const int n0 = blockIdx.x * 64;
    const int tid = threadIdx.x;

    for (int i = tid; i < 4096; i += 256) {
        int j = i * 4;
        int k = j >> 7, c = j & 127;
        *(float4*)&Ws[j] = *(const float4*)&W[(size_t)k * HF + ct * 128 + c];
    }
    for (int i = tid; i < 2048; i += 256) {
        int j = i * 4;
        int nn = j >> 7, c = j & 127;
        int n = n0 + nn;
        float4 v = make_float4(0.f, 0.f, 0.f, 0.f);
        if (n < N_NODES) v = *(const float4*)&h[(size_t)n * DIN + c];
        *(float4*)&hs[j] = v;
    }
    __syncthreads();

    const int tx = tid & 31, ty = tid >> 5;
    float acc[8][4];
#pragma unroll
    for (int i = 0; i < 8; i++) { acc[i][0] = acc[i][1] = acc[i][2] = acc[i][3] = 0.f; }

#pragma unroll 4
    for (int k = 0; k < 128; k++) {
        float4 b = *(float4*)&Ws[k * 128 + tx * 4];
#pragma unroll
        for (int i = 0; i < 8; i++) {
            float a = hs[(ty * 8 + i) * 128 + k];
            acc[i][0] += a * b.x; acc[i][1] += a * b.y;
            acc[i][2] += a * b.z; acc[i][3] += a * b.w;
        }
    }
#pragma unroll
    for (int i = 0; i < 8; i++) {
        int n = n0 + ty * 8 + i;
        if (n < N_NODES)
            *(float4*)&feat[(size_t)n * HF + ct * 128 + tx * 4] =
                make_float4(acc[i][0], acc[i][1], acc[i][2], acc[i][3]);
    }
}

// ---------------- el/er ------------------------------------------------------
__global__ void elrer_kernel(const float* __restrict__ feat, const float* __restrict__ al,
                             const float* __restrict__ ar, float* __restrict__ el,
                             float* __restrict__ er, int F) {
    int g = blockIdx.x * blockDim.x + threadIdx.x;
    if (g >= N_NODES * NH) return;
    int n = g >> 2, hh = g & 3;
    const float* fr = feat + (size_t)n * NH * F + hh * F;
    const float* alr = al + hh * F;
    const float* arr = ar + hh * F;
    float sl = 0.f, sr = 0.f;
    for (int f = 0; f < F; f++) { float v = fr[f]; sl += v * alr[f]; sr += v * arr[f]; }
    el[g] = sl; er[g] = sr;
}

// ---------------- CSR build --------------------------------------------------
__global__ void zero_cnt() {
    int i = blockIdx.x * blockDim.x + threadIdx.x;
    if (i < N_NODES) g_cnt[i] = 0;
}
__global__ void hist_kernel(const int* __restrict__ dst) {
    int e = blockIdx.x * blockDim.x + threadIdx.x;
    if (e < N_EDGES) atomicAdd(&g_cnt[dst[e]], 1);
}
__global__ void scan1_kernel() {   // 512-wide block scans
    __shared__ int sm[512];
    int t = threadIdx.x;
    int i = blockIdx.x * 512 + t;
    int v = (i < N_NODES) ? g_cnt[i] : 0;
    sm[t] = v; __syncthreads();
    for (int off = 1; off < 512; off <<= 1) {
        int x = (t >= off) ? sm[t - off] : 0;
        __syncthreads();
        sm[t] += x; __syncthreads();
    }
    if (i < N_NODES) g_rptr[i] = sm[t] - v;            // block-local exclusive
    if (t == 511) g_bsum[blockIdx.x] = sm[511];
}
__global__ void scan2_kernel(int nb) {  // single block, scan block sums
    __shared__ int sm[256];
    int t = threadIdx.x;
    int v = (t < nb) ? g_bsum[t] : 0;
    sm[t] = v; __syncthreads();
    for (int off = 1; off < 256; off <<= 1) {
        int x = (t >= off) ? sm[t - off] : 0;
        __syncthreads();
        sm[t] += x; __syncthreads();
    }
    if (t < nb) g_bsum[t] = sm[t] - v;                 // exclusive
}
__global__ void scan3_kernel() {
    int i = blockIdx.x * blockDim.x + threadIdx.x;
    if (i < N_NODES) {
        int r = g_rptr[i] + g_bsum[i >> 9];
        g_rptr[i] = r;
        g_cursor[i] = r;
    }
    if (i == 0) g_rptr[N_NODES] = N_EDGES;
}
__global__ void scatter_kernel(const int* __restrict__ src, const int* __restrict__ dst) {
    int e = blockIdx.x * blockDim.x + threadIdx.x;
    if (e >= N_EDGES) return;
    int pos = atomicAdd(&g_cursor[dst[e]], 1);
    g_srcs[pos] = src[e];
}

// ---------------- fused GAT aggregation: one warp per dst node ---------------
// Computes out[d] = activation( (sum_e ex_e * feat[src_e]) / sum_e ex_e + bias )
// where ex = exp(lrelu(el[src]+er[dst])) (softmax max-shift dropped: invariant).
// HF=128 (Q=4, head=q) or HF=256 (Q=8, head=q>>1). LAST fuses head-mean to y.
template<int HF, bool LAST>
__global__ void gat_agg(const float* __restrict__ feat, const float* __restrict__ el,
                        const float* __restrict__ er, const float* __restrict__ bias,
                        float* __restrict__ out) {
    constexpr int Q = HF / 32;
    int warp = (blockIdx.x * blockDim.x + threadIdx.x) >> 5;
    int lane = threadIdx.x & 31;
    if (warp >= N_NODES) return;
    const int nid = warp;

    float4 erv = *(const float4*)&er[nid * 4];
    int beg = g_rptr[nid], end = g_rptr[nid + 1];

    float acc[Q];
#pragma unroll
    for (int q = 0; q < Q; q++) acc[q] = 0.f;
    float den0 = 0.f, den1 = 0.f, den2 = 0.f, den3 = 0.f;

    for (int i = beg; i < end; i++) {
        int s = __ldg(&g_srcs[i]);                       // warp-uniform
        float4 elv = *(const float4*)&el[s * 4];         // broadcast (16B)
        float ex0 = __expf(lrelu(elv.x + erv.x));
        float ex1 = __expf(lrelu(elv.y + erv.y));
        float ex2 = __expf(lrelu(elv.z + erv.z));
        float ex3 = __expf(lrelu(elv.w + erv.w));
        den0 += ex0; den1 += ex1; den2 += ex2; den3 += ex3;
        const float* fp = feat + (size_t)s * HF + lane;
#pragma unroll
        for (int q = 0; q < Q; q++) {
            int head = (HF == 128) ? q : (q >> 1);
            float ex = (head == 0) ? ex0 : (head == 1) ? ex1 : (head == 2) ? ex2 : ex3;
            acc[q] += ex * fp[q * 32];
        }
    }

    float inv[4];
    inv[0] = 1.f / fmaxf(den0, 1e-9f);
    inv[1] = 1.f / fmaxf(den1, 1e-9f);
    inv[2] = 1.f / fmaxf(den2, 1e-9f);
    inv[3] = 1.f / fmaxf(den3, 1e-9f);

    if (!LAST) {
#pragma unroll
        for (int q = 0; q < Q; q++) {
            int col = q * 32 + lane;
            float v = acc[q] * inv[q] + bias[col];
            v = v > 0.f ? v : expm1f(v);                 // ELU
            out[(size_t)nid * HF + col] = v;
        }
    } else {
        // HF=256, F=64: col = q*32+lane, head=q>>1, f=(q&1)*32+lane; mean over heads
        float y0 = 0.f, y1 = 0.f;
#pragma unroll
        for (int q = 0; q < Q; q++) {
            int h = q >> 1;
            float v = acc[q] * inv[h] + bias[h * 64 + (q & 1) * 32 + lane];
            if (q & 1) y1 += v; else y0 += v;
        }
        out[(size_t)nid * 64 + lane]      = 0.25f * y0;
        out[(size_t)nid * 64 + 32 + lane] = 0.25f * y1;
    }
}

// ---------------- host -------------------------------------------------------
extern "C" void kernel_launch(void* const* d_in, const int* in_sizes, int n_in,
                              void* d_out, int out_size) {
    const float* x   = (const float*)d_in[0];
    const int*   src = (const int*)d_in[1];
    const int*   dst = (const int*)d_in[2];
    const float *W[4], *al[4], *ar[4], *bb[4];
    for (int i = 0; i < 4; i++) {
        W[i]  = (const float*)d_in[3 + i * 4];
        al[i] = (const float*)d_in[4 + i * 4];
        ar[i] = (const float*)d_in[5 + i * 4];
        bb[i] = (const float*)d_in[6 + i * 4];
    }

    float *feat, *A, *B, *el, *er;
    cudaGetSymbolAddress((void**)&feat, g_feat);
    cudaGetSymbolAddress((void**)&A,    g_bufA);
    cudaGetSymbolAddress((void**)&B,    g_bufB);
    cudaGetSymbolAddress((void**)&el,   g_el);
    cudaGetSymbolAddress((void**)&er,   g_er);

    cudaFuncSetAttribute(gemm_kernel, cudaFuncAttributeMaxDynamicSharedMemorySize, 98304);

    // ---- one-time CSR build (dst-sorted) ----
    const int nb = (N_NODES + 511) / 512;   // 98
    zero_cnt<<<(N_NODES + 255) / 256, 256>>>();
    hist_kernel<<<(N_EDGES + 255) / 256, 256>>>(dst);
    scan1_kernel<<<nb, 512>>>();
    scan2_kernel<<<1, 256>>>(nb);
    scan3_kernel<<<(N_NODES + 255) / 256, 256>>>();
    scatter_kernel<<<(N_EDGES + 255) / 256, 256>>>(src, dst);

    const int agg_blocks = (N_NODES * 32 + 255) / 256;

    // ---- layer 1: x -> A ----
    gemm_kernel<<<dim3((N_NODES + 63) / 64, 1), 256, 98304>>>(x, W[0], feat, 128);
    elrer_kernel<<<(N_NODES * NH + 255) / 256, 256>>>(feat, al[0], ar[0], el, er, 32);
    gat_agg<128, false><<<agg_blocks, 256>>>(feat, el, er, bb[0], A);

    // ---- layer 2: A -> B ----
    gemm_kernel<<<dim3((N_NODES + 63) / 64, 1), 256, 98304>>>(A, W[1], feat, 128);
    elrer_kernel<<<(N_NODES * NH + 255) / 256, 256>>>(feat, al[1], ar[1], el, er, 32);
    gat_agg<128, false><<<agg_blocks, 256>>>(feat, el, er, bb[1], B);

    // ---- layer 3: B -> A ----
    gemm_kernel<<<dim3((N_NODES + 63) / 64, 1), 256, 98304>>>(B, W[2], feat, 128);
    elrer_kernel<<<(N_NODES * NH + 255) / 256, 256>>>(feat, al[2], ar[2], el, er, 32);
    gat_agg<128, false><<<agg_blocks, 256>>>(feat, el, er, bb[2], A);

    // ---- layer 4: A -> d_out (fused head-mean) ----
    gemm_kernel<<<dim3((N_NODES + 63) / 64, 2), 256, 98304>>>(A, W[3], feat, 256);
    elrer_kernel<<<(N_NODES * NH + 255) / 256, 256>>>(feat, al[3], ar[3], el, er, 64);
    gat_agg<256, true><<<agg_blocks, 256>>>(feat, el, er, bb[3], (float*)d_out);
}

// round 3
// speedup vs baseline: 2.0899x; 1.2236x over previous
#include <cuda_runtime.h>
#include <cuda_fp16.h>
#include <math.h>

#define N_NODES 50000
#define N_EDGES 800000
#define DIN 128
#define NH 4

// ---------------- scratch buffers -------------------------------------------
__device__ __half g_feath[(size_t)N_NODES * 256];  // GEMM output, fp16 (max HF=256)
__device__ float  g_bufA[(size_t)N_NODES * 128];   // activations
__device__ float  g_bufB[(size_t)N_NODES * 128];   // activations
__device__ float  g_el[(size_t)N_NODES * NH];
__device__ float  g_er[(size_t)N_NODES * NH];
__device__ int    g_cnt[N_NODES];
__device__ int    g_rptr[N_NODES + 1];
__device__ int    g_cursor[N_NODES];
__device__ int    g_bsum[256];
__device__ int    g_srcs[N_EDGES];

// ---------------- helpers ----------------------------------------------------
__device__ __forceinline__ float lrelu(float v) { return v > 0.f ? v : 0.2f * v; }

// ---------------- GEMM + fused el/er + fp16 feat output ----------------------
// feat = h @ W  (K = 128). Per column-tile of 128, each thread owns 8 nodes x 4
// cols (one head's worth: 4 cols never straddle an F-boundary). el/er computed
// exactly from fp32 accumulators via width-(F/4) shuffle reductions.
template<int F>
__global__ void gemm_el_kernel(const float* __restrict__ h, const float* __restrict__ W,
                               const float* __restrict__ al, const float* __restrict__ ar,
                               __half* __restrict__ feat, float* __restrict__ el,
                               float* __restrict__ er) {
    constexpr int HF = 4 * F;
    extern __shared__ float sm[];
    float* Ws = sm;                 // [128][128]
    float* hs = sm + 128 * 128;     // [64][128]
    const int ct = blockIdx.y;
    const int n0 = blockIdx.x * 64;
    const int tid = threadIdx.x;

    for (int i = tid; i < 4096; i += 256) {
        int j = i * 4;
        int k = j >> 7, c = j & 127;
        *(float4*)&Ws[j] = *(const float4*)&W[(size_t)k * HF + ct * 128 + c];
    }
    for (int i = tid; i < 2048; i += 256) {
        int j = i * 4;
        int nn = j >> 7, c = j & 127;
        int n = n0 + nn;
        float4 v = make_float4(0.f, 0.f, 0.f, 0.f);
        if (n < N_NODES) v = *(const float4*)&h[(size_t)n * DIN + c];
        *(float4*)&hs[j] = v;
    }
    __syncthreads();

    const int tx = tid & 31, ty = tid >> 5;
    float acc[8][4];
#pragma unroll
    for (int i = 0; i < 8; i++) { acc[i][0] = acc[i][1] = acc[i][2] = acc[i][3] = 0.f; }

#pragma unroll 4
    for (int k = 0; k < 128; k++) {
        float4 b = *(float4*)&Ws[k * 128 + tx * 4];
#pragma unroll
        for (int i = 0; i < 8; i++) {
            float a = hs[(ty * 8 + i) * 128 + k];
            acc[i][0] += a * b.x; acc[i][1] += a * b.y;
            acc[i][2] += a * b.z; acc[i][3] += a * b.w;
        }
    }

    // epilogue: el/er partials + fp16 store
    const int c0 = ct * 128 + tx * 4;            // global col of this thread's 4
    const int head = c0 / F;
    const int f0 = c0 % F;
    float alv[4], arv[4];
#pragma unroll
    for (int c = 0; c < 4; c++) {
        alv[c] = __ldg(&al[head * F + f0 + c]);
        arv[c] = __ldg(&ar[head * F + f0 + c]);
    }
    constexpr int GW = F / 4;                    // lanes per head group (8 or 16)

#pragma unroll
    for (int i = 0; i < 8; i++) {
        int n = n0 + ty * 8 + i;
        float pl = acc[i][0] * alv[0] + acc[i][1] * alv[1]
                 + acc[i][2] * alv[2] + acc[i][3] * alv[3];
        float pr = acc[i][0] * arv[0] + acc[i][1] * arv[1]
                 + acc[i][2] * arv[2] + acc[i][3] * arv[3];
#pragma unroll
        for (int off = GW / 2; off > 0; off >>= 1) {
            pl += __shfl_down_sync(0xffffffffu, pl, off, GW);
            pr += __shfl_down_sync(0xffffffffu, pr, off, GW);
        }
        if (n < N_NODES) {
            if ((tx & (GW - 1)) == 0) {
                el[n * 4 + head] = pl;
                er[n * 4 + head] = pr;
            }
            __half2* fp = (__half2*)&feat[(size_t)n * HF + c0];
            fp[0] = __floats2half2_rn(acc[i][0], acc[i][1]);
            fp[1] = __floats2half2_rn(acc[i][2], acc[i][3]);
        }
    }
}

// ---------------- CSR build --------------------------------------------------
__global__ void zero_cnt() {
    int i = blockIdx.x * blockDim.x + threadIdx.x;
    if (i < N_NODES) g_cnt[i] = 0;
}
__global__ void hist_kernel(const int* __restrict__ dst) {
    int e = blockIdx.x * blockDim.x + threadIdx.x;
    if (e < N_EDGES) atomicAdd(&g_cnt[dst[e]], 1);
}
__global__ void scan1_kernel() {
    __shared__ int sm[512];
    int t = threadIdx.x;
    int i = blockIdx.x * 512 + t;
    int v = (i < N_NODES) ? g_cnt[i] : 0;
    sm[t] = v; __syncthreads();
    for (int off = 1; off < 512; off <<= 1) {
        int x = (t >= off) ? sm[t - off] : 0;
        __syncthreads();
        sm[t] += x; __syncthreads();
    }
    if (i < N_NODES) g_rptr[i] = sm[t] - v;
    if (t == 511) g_bsum[blockIdx.x] = sm[511];
}
__global__ void scan2_kernel(int nb) {
    __shared__ int sm[256];
    int t = threadIdx.x;
    int v = (t < nb) ? g_bsum[t] : 0;
    sm[t] = v; __syncthreads();
    for (int off = 1; off < 256; off <<= 1) {
        int x = (t >= off) ? sm[t - off] : 0;
        __syncthreads();
        sm[t] += x; __syncthreads();
    }
    if (t < nb) g_bsum[t] = sm[t] - v;
}
__global__ void scan3_kernel() {
    int i = blockIdx.x * blockDim.x + threadIdx.x;
    if (i < N_NODES) {
        int r = g_rptr[i] + g_bsum[i >> 9];
        g_rptr[i] = r;
        g_cursor[i] = r;
    }
    if (i == 0) g_rptr[N_NODES] = N_EDGES;
}
__global__ void scatter_kernel(const int* __restrict__ src, const int* __restrict__ dst) {
    int e = blockIdx.x * blockDim.x + threadIdx.x;
    if (e >= N_EDGES) return;
    int pos = atomicAdd(&g_cursor[dst[e]], 1);
    g_srcs[pos] = src[e];
}

// ---------------- fused GAT aggregation: one warp per dst node ---------------
// out[d] = act( (sum_e ex_e * feat16[src_e]) / sum_e ex_e + bias ),
// ex = exp(lrelu(el[src]+er[dst])). fp16 gather, fp32 accumulate.
template<int HF, bool LAST>
__global__ void gat_agg(const __half* __restrict__ feat, const float* __restrict__ el,
                        const float* __restrict__ er, const float* __restrict__ bias,
                        float* __restrict__ out) {
    constexpr int Q = HF / 64;                   // half2 per lane (2 or 4)
    int warp = (blockIdx.x * blockDim.x + threadIdx.x) >> 5;
    int lane = threadIdx.x & 31;
    if (warp >= N_NODES) return;
    const int nid = warp;

    float4 erv = *(const float4*)&er[nid * 4];
    int beg = g_rptr[nid], end = g_rptr[nid + 1];

    float2 acc[Q];
#pragma unroll
    for (int q = 0; q < Q; q++) acc[q] = make_float2(0.f, 0.f);
    float den0 = 0.f, den1 = 0.f, den2 = 0.f, den3 = 0.f;
    const int hsel = lane >> 4;                  // head selector for HF=128

#pragma unroll 2
    for (int i = beg; i < end; i++) {
        int s = __ldg(&g_srcs[i]);
        float4 elv = *(const float4*)&el[s * 4];
        float ex0 = __expf(lrelu(elv.x + erv.x));
        float ex1 = __expf(lrelu(elv.y + erv.y));
        float ex2 = __expf(lrelu(elv.z + erv.z));
        float ex3 = __expf(lrelu(elv.w + erv.w));
        den0 += ex0; den1 += ex1; den2 += ex2; den3 += ex3;
        const __half2* fp = (const __half2*)(feat + (size_t)s * HF);
#pragma unroll
        for (int q = 0; q < Q; q++) {
            // half2 index j = q*32+lane; head = (HF==128) ? j>>4 : q
            float ex;
            if (HF == 128) {
                if (q == 0) ex = hsel ? ex1 : ex0;
                else        ex = hsel ? ex3 : ex2;
            } else {
                ex = (q == 0) ? ex0 : (q == 1) ? ex1 : (q == 2) ? ex2 : ex3;
            }
            float2 f = __half22float2(fp[q * 32 + lane]);
            acc[q].x += ex * f.x;
            acc[q].y += ex * f.y;
        }
    }

    float inv[4];
    inv[0] = 1.f / fmaxf(den0, 1e-9f);
    inv[1] = 1.f / fmaxf(den1, 1e-9f);
    inv[2] = 1.f / fmaxf(den2, 1e-9f);
    inv[3] = 1.f / fmaxf(den3, 1e-9f);

    if (!LAST) {
        // HF=128: cols (2j, 2j+1), j = q*32+lane, head = j>>4
#pragma unroll
        for (int q = 0; q < Q; q++) {
            int j = q * 32 + lane;
            int hh = j >> 4;
            int col = 2 * j;
            float vx = acc[q].x * inv[hh] + bias[col];
            float vy = acc[q].y * inv[hh] + bias[col + 1];
            vx = vx > 0.f ? vx : expm1f(vx);
            vy = vy > 0.f ? vy : expm1f(vy);
            *(float2*)&out[(size_t)nid * HF + col] = make_float2(vx, vy);
        }
    } else {
        // HF=256: head = q, f = 2*lane (+1); mean over 4 heads
        float yx = 0.f, yy = 0.f;
#pragma unroll
        for (int q = 0; q < Q; q++) {
            yx += acc[q].x * inv[q] + bias[q * 64 + 2 * lane];
            yy += acc[q].y * inv[q] + bias[q * 64 + 2 * lane + 1];
        }
        *(float2*)&out[(size_t)nid * 64 + 2 * lane] = make_float2(0.25f * yx, 0.25f * yy);
    }
}

// ---------------- host -------------------------------------------------------
extern "C" void kernel_launch(void* const* d_in, const int* in_sizes, int n_in,
                              void* d_out, int out_size) {
    const float* x   = (const float*)d_in[0];
    const int*   src = (const int*)d_in[1];
    const int*   dst = (const int*)d_in[2];
    const float *W[4], *al[4], *ar[4], *bb[4];
    for (int i = 0; i < 4; i++) {
        W[i]  = (const float*)d_in[3 + i * 4];
        al[i] = (const float*)d_in[4 + i * 4];
        ar[i] = (const float*)d_in[5 + i * 4];
        bb[i] = (const float*)d_in[6 + i * 4];
    }

    __half* feat;
    float *A, *B, *el, *er;
    cudaGetSymbolAddress((void**)&feat, g_feath);
    cudaGetSymbolAddress((void**)&A,    g_bufA);
    cudaGetSymbolAddress((void**)&B,    g_bufB);
    cudaGetSymbolAddress((void**)&el,   g_el);
    cudaGetSymbolAddress((void**)&er,   g_er);

    cudaFuncSetAttribute(gemm_el_kernel<32>, cudaFuncAttributeMaxDynamicSharedMemorySize, 98304);
    cudaFuncSetAttribute(gemm_el_kernel<64>, cudaFuncAttributeMaxDynamicSharedMemorySize, 98304);

    // ---- one-time CSR build (dst-sorted) ----
    const int nb = (N_NODES + 511) / 512;
    zero_cnt<<<(N_NODES + 255) / 256, 256>>>();
    hist_kernel<<<(N_EDGES + 255) / 256, 256>>>(dst);
    scan1_kernel<<<nb, 512>>>();
    scan2_kernel<<<1, 256>>>(nb);
    scan3_kernel<<<(N_NODES + 255) / 256, 256>>>();
    scatter_kernel<<<(N_EDGES + 255) / 256, 256>>>(src, dst);

    const int agg_blocks = (N_NODES * 32 + 255) / 256;
    const dim3 g1((N_NODES + 63) / 64, 1), g2((N_NODES + 63) / 64, 2);

    // ---- layer 1: x -> A ----
    gemm_el_kernel<32><<<g1, 256, 98304>>>(x, W[0], al[0], ar[0], feat, el, er);
    gat_agg<128, false><<<agg_blocks, 256>>>(feat, el, er, bb[0], A);
    // ---- layer 2: A -> B ----
    gemm_el_kernel<32><<<g1, 256, 98304>>>(A, W[1], al[1], ar[1], feat, el, er);
    gat_agg<128, false><<<agg_blocks, 256>>>(feat, el, er, bb[1], B);
    // ---- layer 3: B -> A ----
    gemm_el_kernel<32><<<g1, 256, 98304>>>(B, W[2], al[2], ar[2], feat, el, er);
    gat_agg<128, false><<<agg_blocks, 256>>>(feat, el, er, bb[2], A);
    // ---- layer 4: A -> d_out (fused head-mean) ----
    gemm_el_kernel<64><<<g2, 256, 98304>>>(A, W[3], al[3], ar[3], feat, el, er);
    gat_agg<256, true><<<agg_blocks, 256>>>(feat, el, er, bb[3], (float*)d_out);
}

// round 4
// speedup vs baseline: 3.0796x; 1.4736x over previous
#include <cuda_runtime.h>
#include <cuda_fp16.h>
#include <math.h>

#define N_NODES 50000
#define N_EDGES 800000
#define DIN 128
#define NH 4

// ---------------- scratch buffers -------------------------------------------
__device__ __half g_feath[(size_t)N_NODES * 256];  // GEMM output fp16 (max HF=256)
__device__ float  g_bufA[(size_t)N_NODES * 128];
__device__ float  g_bufB[(size_t)N_NODES * 128];
__device__ float  g_el[(size_t)N_NODES * NH];
__device__ float  g_er[(size_t)N_NODES * NH];
__device__ int    g_cnt[N_NODES];
__device__ int    g_rptr[N_NODES + 1];
__device__ int    g_cursor[N_NODES];
__device__ int    g_srcs[N_EDGES];

__device__ __forceinline__ float lrelu(float v) { return v > 0.f ? v : 0.2f * v; }

// ---------------- tensor-core GEMM + fused el/er -----------------------------
// feat[n, ct*128 + c] = sum_k h[n,k] * W[k, ct*128+c], fp16 inputs, fp32 accum.
// Block: 256 thr (8 warps), tile M=128 N=128 K=128. mma.sync.m16n8k16.
// Epilogue: fp16 feat store + exact el/er (al/ar flat index == global col).
template<int F>
__global__ void tc_gemm(const float* __restrict__ h, const float* __restrict__ W,
                        const float* __restrict__ al, const float* __restrict__ ar,
                        __half* __restrict__ feat, float* __restrict__ el,
                        float* __restrict__ er) {
    constexpr int HF = 4 * F;
    constexpr int HT = 128 / F;            // heads per 128-col tile
    extern __shared__ __half smx[];
    __half* As = smx;                      // [128][136] row-major (m,k)
    __half* Bs = smx + 128 * 136;          // [128][136] n-major over k, swizzled
    float* sAL = (float*)(smx + 2 * 128 * 136);
    float* sAR = sAL + 128;

    const int ct  = blockIdx.y;
    const int n0  = blockIdx.x * 128;
    const int tid = threadIdx.x;
    const int lane = tid & 31;
    const int wid  = tid >> 5;

    if (tid < 128) { sAL[tid] = al[ct * 128 + tid]; sAR[tid] = ar[ct * 128 + tid]; }

    // A tile: h fp32 -> As fp16  (128x128)
#pragma unroll
    for (int i = 0; i < 16; i++) {
        int idx = tid + i * 256;           // 4096 float4 slots
        int j = idx * 4;
        int r = j >> 7, c = j & 127;
        int n = n0 + r;
        float4 v = make_float4(0.f, 0.f, 0.f, 0.f);
        if (n < N_NODES) v = *(const float4*)&h[(size_t)n * DIN + c];
        __half2* p = (__half2*)&As[r * 136 + c];
        p[0] = __floats2half2_rn(v.x, v.y);
        p[1] = __floats2half2_rn(v.z, v.w);
    }
    // B tile transposed: Bs[n][kpair^sw] = (W[2kp][n], W[2kp+1][n])
#pragma unroll
    for (int i = 0; i < 32; i++) {
        int t = tid + i * 256;             // n in [0,128), kp in [0,64)
        int n = t & 127, kp = t >> 7;
        int k = kp * 2;
        float f0 = W[(size_t)k * HF + ct * 128 + n];
        float f1 = W[(size_t)(k + 1) * HF + ct * 128 + n];
        int kps = kp ^ ((n >> 3) & 3);
        *(__half2*)&Bs[n * 136 + kps * 2] = __floats2half2_rn(f0, f1);
    }
    __syncthreads();

    const int g = lane >> 2, q = lane & 3;
    const int m0 = wid * 16;
    float acc[16][4];
#pragma unroll
    for (int nt = 0; nt < 16; nt++)
        acc[nt][0] = acc[nt][1] = acc[nt][2] = acc[nt][3] = 0.f;

#pragma unroll
    for (int ks = 0; ks < 8; ks++) {
        unsigned a0 = *(const unsigned*)&As[(m0 + g)     * 136 + ks * 16 + q * 2];
        unsigned a1 = *(const unsigned*)&As[(m0 + 8 + g) * 136 + ks * 16 + q * 2];
        unsigned a2 = *(const unsigned*)&As[(m0 + g)     * 136 + ks * 16 + 8 + q * 2];
        unsigned a3 = *(const unsigned*)&As[(m0 + 8 + g) * 136 + ks * 16 + 8 + q * 2];
#pragma unroll
        for (int nt = 0; nt < 16; nt++) {
            int n = nt * 8 + g;
            int sw = nt & 3;
            int p0 = (ks * 8 + q) ^ sw;
            int p1 = (ks * 8 + 4 + q) ^ sw;
            unsigned b0 = *(const unsigned*)&Bs[n * 136 + p0 * 2];
            unsigned b1 = *(const unsigned*)&Bs[n * 136 + p1 * 2];
            asm volatile(
                "mma.sync.aligned.m16n8k16.row.col.f32.f16.f16.f32 "
                "{%0,%1,%2,%3}, {%4,%5,%6,%7}, {%8,%9}, {%0,%1,%2,%3};"
                : "+f"(acc[nt][0]), "+f"(acc[nt][1]), "+f"(acc[nt][2]), "+f"(acc[nt][3])
                : "r"(a0), "r"(a1), "r"(a2), "r"(a3), "r"(b0), "r"(b1));
        }
    }

    const int rA = n0 + m0 + g, rB = rA + 8;

    // feat fp16 store
#pragma unroll
    for (int nt = 0; nt < 16; nt++) {
        int col = ct * 128 + nt * 8 + q * 2;
        if (rA < N_NODES)
            *(__half2*)&feat[(size_t)rA * HF + col] = __floats2half2_rn(acc[nt][0], acc[nt][1]);
        if (rB < N_NODES)
            *(__half2*)&feat[(size_t)rB * HF + col] = __floats2half2_rn(acc[nt][2], acc[nt][3]);
    }
    // el/er: per head, sum over that head's columns, quad-reduce
#pragma unroll
    for (int hh = 0; hh < HT; hh++) {
        float plA = 0.f, prA = 0.f, plB = 0.f, prB = 0.f;
#pragma unroll
        for (int j = 0; j < F / 8; j++) {
            int nt = hh * (F / 8) + j;
            int c = nt * 8 + q * 2;
            float al0 = sAL[c], al1 = sAL[c + 1];
            float ar0 = sAR[c], ar1 = sAR[c + 1];
            plA += acc[nt][0] * al0 + acc[nt][1] * al1;
            prA += acc[nt][0] * ar0 + acc[nt][1] * ar1;
            plB += acc[nt][2] * al0 + acc[nt][3] * al1;
            prB += acc[nt][2] * ar0 + acc[nt][3] * ar1;
        }
        plA += __shfl_xor_sync(~0u, plA, 1); plA += __shfl_xor_sync(~0u, plA, 2);
        prA += __shfl_xor_sync(~0u, prA, 1); prA += __shfl_xor_sync(~0u, prA, 2);
        plB += __shfl_xor_sync(~0u, plB, 1); plB += __shfl_xor_sync(~0u, plB, 2);
        prB += __shfl_xor_sync(~0u, prB, 1); prB += __shfl_xor_sync(~0u, prB, 2);
        if (q == 0) {
            int head = ct * HT + hh;
            if (rA < N_NODES) { el[rA * 4 + head] = plA; er[rA * 4 + head] = prA; }
            if (rB < N_NODES) { el[rB * 4 + head] = plB; er[rB * 4 + head] = prB; }
        }
    }
}

// ---------------- CSR build --------------------------------------------------
__global__ void hist_kernel(const int* __restrict__ dst) {
    int e = blockIdx.x * blockDim.x + threadIdx.x;
    if (e < N_EDGES) atomicAdd(&g_cnt[dst[e]], 1);
}
// single-block chained scan over 50000 counts
__global__ void scan_kernel() {
    __shared__ int wsum[32];
    __shared__ int carry;
    int t = threadIdx.x;
    if (t == 0) carry = 0;
    __syncthreads();
    for (int base = 0; base < N_NODES; base += 1024) {
        int i = base + t;
        int v = (i < N_NODES) ? g_cnt[i] : 0;
        int x = v;
#pragma unroll
        for (int o = 1; o < 32; o <<= 1) {
            int y = __shfl_up_sync(~0u, x, o);
            if ((t & 31) >= o) x += y;
        }
        if ((t & 31) == 31) wsum[t >> 5] = x;
        __syncthreads();
        if (t < 32) {
            int s = wsum[t];
#pragma unroll
            for (int o = 1; o < 32; o <<= 1) {
                int y = __shfl_up_sync(~0u, s, o);
                if (t >= o) s += y;
            }
            wsum[t] = s;
        }
        __syncthreads();
        int warpoff = (t >= 32) ? wsum[(t >> 5) - 1] : 0;
        int excl = x + warpoff - v + carry;
        if (i < N_NODES) { g_rptr[i] = excl; g_cursor[i] = excl; }
        int btot = wsum[31];
        __syncthreads();
        if (t == 0) carry += btot;
        __syncthreads();
    }
    if (t == 0) g_rptr[N_NODES] = N_EDGES;
}
__global__ void scatter_kernel(const int* __restrict__ src, const int* __restrict__ dst) {
    int e = blockIdx.x * blockDim.x + threadIdx.x;
    if (e >= N_EDGES) return;
    int pos = atomicAdd(&g_cursor[dst[e]], 1);
    g_srcs[pos] = src[e];
}

// ---------------- fused GAT aggregation: one warp per dst node ---------------
template<int HF, bool LAST>
__global__ void gat_agg(const __half* __restrict__ feat, const float* __restrict__ el,
                        const float* __restrict__ er, const float* __restrict__ bias,
                        float* __restrict__ out) {
    constexpr int Q = HF / 64;
    int warp = (blockIdx.x * blockDim.x + threadIdx.x) >> 5;
    int lane = threadIdx.x & 31;
    if (warp >= N_NODES) return;
    const int nid = warp;

    float4 erv = *(const float4*)&er[nid * 4];
    int beg = g_rptr[nid], end = g_rptr[nid + 1];

    float2 acc[Q];
#pragma unroll
    for (int qq = 0; qq < Q; qq++) acc[qq] = make_float2(0.f, 0.f);
    float den0 = 0.f, den1 = 0.f, den2 = 0.f, den3 = 0.f;
    const int hsel = lane >> 4;

#pragma unroll 2
    for (int i = beg; i < end; i++) {
        int s = __ldg(&g_srcs[i]);
        float4 elv = *(const float4*)&el[s * 4];
        float ex0 = __expf(lrelu(elv.x + erv.x));
        float ex1 = __expf(lrelu(elv.y + erv.y));
        float ex2 = __expf(lrelu(elv.z + erv.z));
        float ex3 = __expf(lrelu(elv.w + erv.w));
        den0 += ex0; den1 += ex1; den2 += ex2; den3 += ex3;
        const __half2* fp = (const __half2*)(feat + (size_t)s * HF);
#pragma unroll
        for (int qq = 0; qq < Q; qq++) {
            float ex;
            if (HF == 128) {
                if (qq == 0) ex = hsel ? ex1 : ex0;
                else         ex = hsel ? ex3 : ex2;
            } else {
                ex = (qq == 0) ? ex0 : (qq == 1) ? ex1 : (qq == 2) ? ex2 : ex3;
            }
            float2 f = __half22float2(fp[qq * 32 + lane]);
            acc[qq].x += ex * f.x;
            acc[qq].y += ex * f.y;
        }
    }

    float inv[4];
    inv[0] = 1.f / fmaxf(den0, 1e-9f);
    inv[1] = 1.f / fmaxf(den1, 1e-9f);
    inv[2] = 1.f / fmaxf(den2, 1e-9f);
    inv[3] = 1.f / fmaxf(den3, 1e-9f);

    if (!LAST) {
#pragma unroll
        for (int qq = 0; qq < Q; qq++) {
            int j = qq * 32 + lane;
            int hh = j >> 4;
            int col = 2 * j;
            float vx = acc[qq].x * inv[hh] + bias[col];
            float vy = acc[qq].y * inv[hh] + bias[col + 1];
            vx = vx > 0.f ? vx : expm1f(vx);
            vy = vy > 0.f ? vy : expm1f(vy);
            *(float2*)&out[(size_t)nid * HF + col] = make_float2(vx, vy);
        }
    } else {
        float yx = 0.f, yy = 0.f;
#pragma unroll
        for (int qq = 0; qq < Q; qq++) {
            yx += acc[qq].x * inv[qq] + bias[qq * 64 + 2 * lane];
            yy += acc[qq].y * inv[qq] + bias[qq * 64 + 2 * lane + 1];
        }
        *(float2*)&out[(size_t)nid * 64 + 2 * lane] = make_float2(0.25f * yx, 0.25f * yy);
    }
}

// ---------------- host -------------------------------------------------------
extern "C" void kernel_launch(void* const* d_in, const int* in_sizes, int n_in,
                              void* d_out, int out_size) {
    const float* x   = (const float*)d_in[0];
    const int*   src = (const int*)d_in[1];
    const int*   dst = (const int*)d_in[2];
    const float *W[4], *al[4], *ar[4], *bb[4];
    for (int i = 0; i < 4; i++) {
        W[i]  = (const float*)d_in[3 + i * 4];
        al[i] = (const float*)d_in[4 + i * 4];
        ar[i] = (const float*)d_in[5 + i * 4];
        bb[i] = (const float*)d_in[6 + i * 4];
    }

    __half* feat;
    float *A, *B, *el, *er;
    int* cnt;
    cudaGetSymbolAddress((void**)&feat, g_feath);
    cudaGetSymbolAddress((void**)&A,    g_bufA);
    cudaGetSymbolAddress((void**)&B,    g_bufB);
    cudaGetSymbolAddress((void**)&el,   g_el);
    cudaGetSymbolAddress((void**)&er,   g_er);
    cudaGetSymbolAddress((void**)&cnt,  g_cnt);

    const int SMEM = 2 * 128 * 136 * 2 + 2 * 128 * 4;   // 70656 B
    cudaFuncSetAttribute(tc_gemm<32>, cudaFuncAttributeMaxDynamicSharedMemorySize, SMEM);
    cudaFuncSetAttribute(tc_gemm<64>, cudaFuncAttributeMaxDynamicSharedMemorySize, SMEM);

    // ---- CSR build: memset + 3 kernels ----
    cudaMemsetAsync(cnt, 0, N_NODES * sizeof(int));
    hist_kernel<<<(N_EDGES + 255) / 256, 256>>>(dst);
    scan_kernel<<<1, 1024>>>();
    scatter_kernel<<<(N_EDGES + 255) / 256, 256>>>(src, dst);

    const int agg_blocks = (N_NODES * 32 + 255) / 256;
    const dim3 g1((N_NODES + 127) / 128, 1), g2((N_NODES + 127) / 128, 2);

    // layer 1
    tc_gemm<32><<<g1, 256, SMEM>>>(x, W[0], al[0], ar[0], feat, el, er);
    gat_agg<128, false><<<agg_blocks, 256>>>(feat, el, er, bb[0], A);
    // layer 2
    tc_gemm<32><<<g1, 256, SMEM>>>(A, W[1], al[1], ar[1], feat, el, er);
    gat_agg<128, false><<<agg_blocks, 256>>>(feat, el, er, bb[1], B);
    // layer 3
    tc_gemm<32><<<g1, 256, SMEM>>>(B, W[2], al[2], ar[2], feat, el, er);
    gat_agg<128, false><<<agg_blocks, 256>>>(feat, el, er, bb[2], A);
    // layer 4 (fused head-mean)
    tc_gemm<64><<<g2, 256, SMEM>>>(A, W[3], al[3], ar[3], feat, el, er);
    gat_agg<256, true><<<agg_blocks, 256>>>(feat, el, er, bb[3], (float*)d_out);
}